// round 11
// baseline (speedup 1.0000x reference)
#include <cuda_runtime.h>
#include <cuda_bf16.h>
#include <cstdint>
#include <math.h>

#define Bb  8
#define Cc  64
#define Hh  128
#define Ww  128
#define HW  (Hh*Ww)
#define K2  9
#define OCT 27
#define CK  (Cc*K2)     // 576

// ---------------------------------------------------------------------------
// helpers
// ---------------------------------------------------------------------------
__device__ __forceinline__ uint32_t smem_to_u32(const void* p) {
    uint32_t a;
    asm("{ .reg .u64 t; cvta.to.shared.u64 t, %1; cvt.u32.u64 %0, t; }"
        : "=r"(a) : "l"(p));
    return a;
}
#define LDSM_X4(r, ad) \
    asm volatile("ldmatrix.sync.aligned.m8n8.x4.shared.b16 {%0,%1,%2,%3}, [%4];" \
        : "=r"((r)[0]), "=r"((r)[1]), "=r"((r)[2]), "=r"((r)[3]) : "r"(ad))
#define LDSM_X4T(r, ad) \
    asm volatile("ldmatrix.sync.aligned.m8n8.x4.trans.shared.b16 {%0,%1,%2,%3}, [%4];" \
        : "=r"((r)[0]), "=r"((r)[1]), "=r"((r)[2]), "=r"((r)[3]) : "r"(ad))
#define STS128(ad, r0, r1, r2, r3) \
    asm volatile("st.shared.v4.b32 [%0], {%1,%2,%3,%4};" \
        :: "r"(ad), "r"(r0), "r"(r1), "r"(r2), "r"(r3) : "memory")
#define MMA_BF16(d, a, b0, b1) \
    asm volatile("mma.sync.aligned.m16n8k16.row.col.f32.bf16.bf16.f32 " \
        "{%0,%1,%2,%3}, {%4,%5,%6,%7}, {%8,%9}, {%0,%1,%2,%3};" \
        : "+f"((d)[0]), "+f"((d)[1]), "+f"((d)[2]), "+f"((d)[3]) \
        : "r"((a)[0]), "r"((a)[1]), "r"((a)[2]), "r"((a)[3]), "r"(b0), "r"(b1))
__device__ __forceinline__ void cp_async16(uint32_t dst, const void* src) {
    asm volatile("cp.async.cg.shared.global [%0], [%1], 16;"
                 :: "r"(dst), "l"(src) : "memory");
}
#define CP_COMMIT() asm volatile("cp.async.commit_group;" ::: "memory")
#define CP_WAIT0()  asm volatile("cp.async.wait_group 0;" ::: "memory")

// ---------------------------------------------------------------------------
// pre-swizzled bf16 B tiles: [9 chunks][64 k-rows x 64 cols], 128B rows, SW128.
__device__ uint4 g_Bh4[9*8192/16];    // deform weights, hi
__device__ uint4 g_Bl4[9*8192/16];    // deform weights, lo
__device__ uint4 g_BOh4[9*8192/16];   // offset+mask weights (cols 0..26), hi
__device__ uint4 g_BOl4[9*8192/16];   // lo

// ---------------------------------------------------------------------------
// Merged weight prep: deform (dw) + offset/mask (ow/mw) -> bf16 hi/lo, k-major
// chunks, SW128 pre-swizzled.
__global__ void prep_all_kernel(const float* __restrict__ dw,
                                const float* __restrict__ ow,
                                const float* __restrict__ mw) {
    int i = blockIdx.x * 256 + threadIdx.x;
    if (i < Cc * CK) {
        int o = i / CK;
        int r = i - o * CK;
        int c = r / 9;
        int k = r - c * 9;
        float v = dw[i];
        __nv_bfloat16 hi = __float2bfloat16(v);
        __nv_bfloat16 lo = __float2bfloat16(v - __bfloat162float(hi));
        uint32_t off = (uint32_t)c * 128u + (uint32_t)o * 2u;
        uint32_t sw  = off ^ ((off >> 3) & 0x70u);
        ((__nv_bfloat16*)g_Bh4)[k * 4096 + (sw >> 1)] = hi;
        ((__nv_bfloat16*)g_Bl4)[k * 4096 + (sw >> 1)] = lo;
        return;
    }
    i -= Cc * CK;
    if (i >= 9 * 64 * 32) return;
    int k = i >> 11;
    int c = (i >> 5) & 63;
    int j = i & 31;
    float v = 0.f;
    if (j < 18)      v = ow[j * CK + c * 9 + k];
    else if (j < 27) v = mw[(j - 18) * CK + c * 9 + k];
    __nv_bfloat16 hi = __float2bfloat16(v);
    __nv_bfloat16 lo = __float2bfloat16(v - __bfloat162float(hi));
    uint32_t off = (uint32_t)c * 128u + (uint32_t)j * 2u;
    uint32_t sw  = off ^ ((off >> 3) & 0x70u);
    ((__nv_bfloat16*)g_BOh4)[k * 4096 + (sw >> 1)] = hi;
    ((__nv_bfloat16*)g_BOl4)[k * 4096 + (sw >> 1)] = lo;
}

// ---------------------------------------------------------------------------
// smem layout (per CTA, 112128 B -> 2 CTAs/SM by regfile):
//   [0, 32768)        B double-buffer: buf*16384, hi @ +0, lo @ +8192
//   [32768, 98304)    A double-buffer: buf*32768, hi @ +0, lo @ +16384
//   [98304, 112128)   s_dy/s_dx/s_mk (128 px x 9 floats each)
#define SM_A0   32768
#define SM_OFF  98304
#define SMEM_F  112128

__device__ __forceinline__ void prefetch_chunk(uint32_t smem_base, int buf,
                                               const uint4* __restrict__ Bh,
                                               const uint4* __restrict__ Bl,
                                               int ch, int tid) {
    const uint32_t dst = smem_base + (uint32_t)buf * 16384u;
    const uint4* sh = Bh + ch * 512;
    const uint4* sl = Bl + ch * 512;
#pragma unroll
    for (int r = 0; r < 2; r++) {
        int i = tid + r * 256;
        cp_async16(dst + (uint32_t)i * 16u, sh + i);
        cp_async16(dst + 8192u + (uint32_t)i * 16u, sl + i);
    }
    CP_COMMIT();
}

// sample quarter q (channels 8q..8q+7 of this thread's 32-ch set), phase 1
__device__ __forceinline__ void p1_quarter(const float* xb, int q, bool ok, int ioff,
                                           uint32_t* hi16, uint32_t* lo16) {
    const float* xc = xb + (size_t)(8 * q) * HW;
#pragma unroll
    for (int j = 0; j < 4; j++) {
        float s0 = ok ? xc[ioff] : 0.f;  xc += HW;
        float s1 = ok ? xc[ioff] : 0.f;  xc += HW;
        const int i = q * 4 + j;
        __nv_bfloat16 h0b = __float2bfloat16(s0);
        __nv_bfloat16 h1b = __float2bfloat16(s1);
        __nv_bfloat162 hp = __nv_bfloat162(h0b, h1b);
        __nv_bfloat162 lp = __floats2bfloat162_rn(s0 - __bfloat162float(h0b),
                                                  s1 - __bfloat162float(h1b));
        hi16[i] = *(uint32_t*)&hp;
        lo16[i] = *(uint32_t*)&lp;
    }
}

// bilinear setup for phase-2 tap t of pixel p at (h,w)
__device__ __forceinline__ void p2_setup(int h, int w, int t, int p,
                                         const float* s_dy, const float* s_dx,
                                         const float* s_mk,
                                         float& w00, float& w01, float& w10, float& w11,
                                         int& i00, int& i01, int& i10, int& i11) {
    const float m  = s_mk[p * 9 + t];
    const float py = (float)(h + t / 3 - 1) + s_dy[p * 9 + t];
    const float px = (float)(w + t % 3 - 1) + s_dx[p * 9 + t];
    const float yf = floorf(py), xf = floorf(px);
    const int   y0 = (int)yf,  x0 = (int)xf;
    const float ly = py - yf,  lx = px - xf;
    const bool y0v = (unsigned)y0       < (unsigned)Hh;
    const bool y1v = (unsigned)(y0 + 1) < (unsigned)Hh;
    const bool x0v = (unsigned)x0       < (unsigned)Ww;
    const bool x1v = (unsigned)(x0 + 1) < (unsigned)Ww;
    w00 = (y0v && x0v) ? (1.f - ly) * (1.f - lx) * m : 0.f;
    w01 = (y0v && x1v) ? (1.f - ly) * lx         * m : 0.f;
    w10 = (y1v && x0v) ? ly         * (1.f - lx) * m : 0.f;
    w11 = (y1v && x1v) ? ly         * lx         * m : 0.f;
    const int cy0 = min(max(y0, 0), Hh - 1), cy1 = min(max(y0 + 1, 0), Hh - 1);
    const int cx0 = min(max(x0, 0), Ww - 1), cx1 = min(max(x0 + 1, 0), Ww - 1);
    i00 = cy0 * Ww + cx0;  i01 = cy0 * Ww + cx1;
    i10 = cy1 * Ww + cx0;  i11 = cy1 * Ww + cx1;
}

// sample quarter q, phase 2 (bilinear, modulated)
__device__ __forceinline__ void p2_quarter(const float* xb, int q,
                                           float w00, float w01, float w10, float w11,
                                           int i00, int i01, int i10, int i11,
                                           uint32_t* hi16, uint32_t* lo16) {
    const float* xc = xb + (size_t)(8 * q) * HW;
#pragma unroll
    for (int j = 0; j < 4; j++) {
        float s0 = w00 * xc[i00] + w01 * xc[i01] + w10 * xc[i10] + w11 * xc[i11];
        xc += HW;
        float s1 = w00 * xc[i00] + w01 * xc[i01] + w10 * xc[i10] + w11 * xc[i11];
        xc += HW;
        const int i = q * 4 + j;
        __nv_bfloat16 h0b = __float2bfloat16(s0);
        __nv_bfloat16 h1b = __float2bfloat16(s1);
        __nv_bfloat162 hp = __nv_bfloat162(h0b, h1b);
        __nv_bfloat162 lp = __floats2bfloat162_rn(s0 - __bfloat162float(h0b),
                                                  s1 - __bfloat162float(h1b));
        hi16[i] = *(uint32_t*)&hp;
        lo16[i] = *(uint32_t*)&lp;
    }
}

// ---------------------------------------------------------------------------
// Fused offset/mask conv + deformable conv.
// One barrier per chunk; A double-buffered; next-chunk sampling interleaved
// into the current chunk's ks/MMA loop (within-warp LDG/MMA overlap).
__global__ __launch_bounds__(256, 2)
void fused_kernel(const float* __restrict__ x,
                  const float* __restrict__ obias,
                  const float* __restrict__ mbias,
                  const float* __restrict__ db,
                  float* __restrict__ out)
{
    extern __shared__ char smd[];
    const uint32_t smem_base = smem_to_u32(smd);
    const int tid = threadIdx.x;

    // sampling-role mapping
    const int set = tid >> 7;        // channel half (32 ch)
    const int p   = tid & 127;       // pixel row within CTA
    const int pixel = blockIdx.x * 128 + p;
    const int b  = pixel >> 14;
    const int hw = pixel & (HW - 1);
    const int h  = hw >> 7;
    const int w  = hw & 127;
    const float* xb = x + (size_t)b * Cc * HW + (size_t)(set * 32) * HW;
    const uint32_t a_row_byte = (uint32_t)p * 128u;
    const uint32_t a_row_sw   = ((uint32_t)(p & 7)) << 4;

    // MMA-role mapping
    const int wid  = tid >> 5;
    const int lane = tid & 31;
    const int m0   = wid * 16;
    const uint32_t lm_arow  = (uint32_t)(m0 + (lane & 15));
    const uint32_t lm_asub  = ((uint32_t)(lane >> 4) & 1u) * 16u;
    const uint32_t lm_asw   = (lm_arow & 7u) << 4;
    const uint32_t lm_abase = lm_arow * 128u;
    const uint32_t lm_bkrow = (uint32_t)(lane & 15);
    const uint32_t lm_bnsub = ((uint32_t)(lane >> 4) & 1u) * 16u;

    float* s_dy = (float*)(smd + SM_OFF);
    float* s_dx = s_dy + 1152;
    float* s_mk = s_dx + 1152;

    uint32_t hi16[16], lo16[16];

    // prologue: BO chunk 0 -> buf0; sample phase-1 chunk 0
    prefetch_chunk(smem_base, 0, g_BOh4, g_BOl4, 0, tid);
    {
        const int hh = h - 1, ww = w - 1;
        const bool ok = ((unsigned)hh < (unsigned)Hh) && ((unsigned)ww < (unsigned)Ww);
        const int ioff = hh * Ww + ww;
#pragma unroll
        for (int q = 0; q < 4; q++) p1_quarter(xb, q, ok, ioff, hi16, lo16);
    }

    // ======================= PHASE 1: offset + mask =======================
    {
        float acc[4][4];
#pragma unroll
        for (int n = 0; n < 4; n++)
#pragma unroll
            for (int q = 0; q < 4; q++) acc[n][q] = 0.f;

        for (int ch = 0; ch < 9; ch++) {
            const uint32_t a_hi = smem_base + SM_A0 + (uint32_t)(ch & 1) * 32768u;
            // stage A(ch) from regs
#pragma unroll
            for (int u = 0; u < 4; u++) {
                uint32_t col = (((uint32_t)set * 64u) + (uint32_t)u * 16u) ^ a_row_sw;
                STS128(a_hi + a_row_byte + col,
                       hi16[u*4+0], hi16[u*4+1], hi16[u*4+2], hi16[u*4+3]);
                STS128(a_hi + 16384u + a_row_byte + col,
                       lo16[u*4+0], lo16[u*4+1], lo16[u*4+2], lo16[u*4+3]);
            }
            CP_WAIT0();        // this thread's B(ch) copies done
            __syncthreads();   // all B(ch)/A(ch) visible; MMA(ch-1) done everywhere

            if (ch < 8) prefetch_chunk(smem_base, (ch + 1) & 1, g_BOh4, g_BOl4, ch + 1, tid);
            else        prefetch_chunk(smem_base, 1, g_Bh4, g_Bl4, 0, tid);  // bridge

            // next-chunk sampling setup (tap ch+1)
            bool ok2 = false; int ioff2 = 0;
            if (ch < 8) {
                const int t = ch + 1;
                const int hh = h + t / 3 - 1, ww = w + t % 3 - 1;
                ok2 = ((unsigned)hh < (unsigned)Hh) && ((unsigned)ww < (unsigned)Ww);
                ioff2 = hh * Ww + ww;
            }

            const uint32_t bh_base = smem_base + (uint32_t)(ch & 1) * 16384u;
            const uint32_t bl_base = bh_base + 8192u;
#pragma unroll
            for (int ks = 0; ks < 4; ks++) {
                uint32_t kcol = (((uint32_t)ks * 32u) + lm_asub) ^ lm_asw;
                uint32_t ah[4], al[4];
                LDSM_X4(ah, a_hi + lm_abase + kcol);
                LDSM_X4(al, a_hi + 16384u + lm_abase + kcol);
                const uint32_t brow = (uint32_t)ks * 16u + lm_bkrow;
                const uint32_t bsw  = (brow & 7u) << 4;
                const uint32_t boff = brow * 128u;
                uint32_t bh[4], bl[4];
                uint32_t ncol = lm_bnsub ^ bsw;
                LDSM_X4T(bh, bh_base + boff + ncol);
                LDSM_X4T(bl, bl_base + boff + ncol);
                MMA_BF16(acc[0], ah, bh[0], bh[1]);
                MMA_BF16(acc[0], ah, bl[0], bl[1]);
                MMA_BF16(acc[0], al, bh[0], bh[1]);
                MMA_BF16(acc[1], ah, bh[2], bh[3]);
                MMA_BF16(acc[1], ah, bl[2], bl[3]);
                MMA_BF16(acc[1], al, bh[2], bh[3]);
                uint32_t ncol2 = (32u + lm_bnsub) ^ bsw;
                LDSM_X4T(bh, bh_base + boff + ncol2);
                LDSM_X4T(bl, bl_base + boff + ncol2);
                MMA_BF16(acc[2], ah, bh[0], bh[1]);
                MMA_BF16(acc[2], ah, bl[0], bl[1]);
                MMA_BF16(acc[2], al, bh[0], bh[1]);
                MMA_BF16(acc[3], ah, bh[2], bh[3]);
                MMA_BF16(acc[3], ah, bl[2], bl[3]);
                MMA_BF16(acc[3], al, bh[2], bh[3]);
                if (ch < 8) p1_quarter(xb, ks, ok2, ioff2, hi16, lo16);
            }
        }

        // epilogue -> smem dy/dx/mask
        const int r0 = m0 + (lane >> 2);
#pragma unroll
        for (int nt = 0; nt < 4; nt++) {
            const int j0 = nt * 8 + (lane & 3) * 2;
#pragma unroll
            for (int q = 0; q < 4; q++) {
                const int j = j0 + (q & 1);
                if (j >= 27) continue;
                const int P = r0 + ((q >> 1) << 3);
                const float v = acc[nt][q];
                if (j < 18) {
                    float t = v + obias[j];
                    if ((j & 1) == 0) s_dy[P * 9 + (j >> 1)] = t;
                    else              s_dx[P * 9 + (j >> 1)] = t;
                } else {
                    float z = v + mbias[j - 18];
                    s_mk[P * 9 + (j - 18)] = 1.f / (1.f + expf(-z));
                }
            }
        }
    }
    __syncthreads();   // offsets visible to deform sampling

    // ========================= PHASE 2: deform ===========================
    float acc2[8][4];
#pragma unroll
    for (int n = 0; n < 8; n++)
#pragma unroll
        for (int q = 0; q < 4; q++) acc2[n][q] = 0.f;

    // sample phase-2 chunk 0
    {
        float w00, w01, w10, w11; int i00, i01, i10, i11;
        p2_setup(h, w, 0, p, s_dy, s_dx, s_mk, w00, w01, w10, w11, i00, i01, i10, i11);
#pragma unroll
        for (int q = 0; q < 4; q++)
            p2_quarter(xb, q, w00, w01, w10, w11, i00, i01, i10, i11, hi16, lo16);
    }

    for (int ch = 0; ch < 9; ch++) {
        const uint32_t a_hi = smem_base + SM_A0 + (uint32_t)(ch & 1) * 32768u;
#pragma unroll
        for (int u = 0; u < 4; u++) {
            uint32_t col = (((uint32_t)set * 64u) + (uint32_t)u * 16u) ^ a_row_sw;
            STS128(a_hi + a_row_byte + col,
                   hi16[u*4+0], hi16[u*4+1], hi16[u*4+2], hi16[u*4+3]);
            STS128(a_hi + 16384u + a_row_byte + col,
                   lo16[u*4+0], lo16[u*4+1], lo16[u*4+2], lo16[u*4+3]);
        }
        CP_WAIT0();
        __syncthreads();

        if (ch < 8) prefetch_chunk(smem_base, ch & 1, g_Bh4, g_Bl4, ch + 1, tid);

        float w00 = 0.f, w01 = 0.f, w10 = 0.f, w11 = 0.f;
        int i00 = 0, i01 = 0, i10 = 0, i11 = 0;
        if (ch < 8)
            p2_setup(h, w, ch + 1, p, s_dy, s_dx, s_mk,
                     w00, w01, w10, w11, i00, i01, i10, i11);

        // deform chunk ch lives in buf (ch+1)&1 (bridge put chunk0 in buf1)
        const uint32_t bh_base = smem_base + (uint32_t)((ch + 1) & 1) * 16384u;
        const uint32_t bl_base = bh_base + 8192u;
#pragma unroll
        for (int ks = 0; ks < 4; ks++) {
            uint32_t kcol = (((uint32_t)ks * 32u) + lm_asub) ^ lm_asw;
            uint32_t ah[4], al[4];
            LDSM_X4(ah, a_hi + lm_abase + kcol);
            LDSM_X4(al, a_hi + 16384u + lm_abase + kcol);
            const uint32_t brow = (uint32_t)ks * 16u + lm_bkrow;
            const uint32_t bsw  = (brow & 7u) << 4;
            const uint32_t boff = brow * 128u;
#pragma unroll
            for (int nt2 = 0; nt2 < 4; nt2++) {
                uint32_t ncol = (((uint32_t)nt2 * 32u) + lm_bnsub) ^ bsw;
                uint32_t bh[4], bl[4];
                LDSM_X4T(bh, bh_base + boff + ncol);
                LDSM_X4T(bl, bl_base + boff + ncol);
                MMA_BF16(acc2[2*nt2],     ah, bh[0], bh[1]);
                MMA_BF16(acc2[2*nt2],     ah, bl[0], bl[1]);
                MMA_BF16(acc2[2*nt2],     al, bh[0], bh[1]);
                MMA_BF16(acc2[2*nt2 + 1], ah, bh[2], bh[3]);
                MMA_BF16(acc2[2*nt2 + 1], ah, bl[2], bl[3]);
                MMA_BF16(acc2[2*nt2 + 1], al, bh[2], bh[3]);
            }
            if (ch < 8)
                p2_quarter(xb, ks, w00, w01, w10, w11, i00, i01, i10, i11, hi16, lo16);
        }
    }

    // ---- epilogue: acc2 fragment -> out[b][o][hw] (+bias) ----
    const int pix0 = blockIdx.x * 128;
    const int bB   = pix0 >> 14;
    const int hw0  = (pix0 & (HW - 1)) + m0 + (lane >> 2);
    float* ob = out + (size_t)bB * Cc * HW;
#pragma unroll
    for (int nt = 0; nt < 8; nt++) {
        const int ch0 = nt * 8 + (lane & 3) * 2;
        const float b0 = db[ch0], b1 = db[ch0 + 1];
        ob[(size_t)ch0       * HW + hw0]     = acc2[nt][0] + b0;
        ob[(size_t)(ch0 + 1) * HW + hw0]     = acc2[nt][1] + b1;
        ob[(size_t)ch0       * HW + hw0 + 8] = acc2[nt][2] + b0;
        ob[(size_t)(ch0 + 1) * HW + hw0 + 8] = acc2[nt][3] + b1;
    }
}

// ---------------------------------------------------------------------------
extern "C" void kernel_launch(void* const* d_in, const int* in_sizes, int n_in,
                              void* d_out, int out_size)
{
    const float* x  = (const float*)d_in[0];
    const float* ow = (const float*)d_in[1];
    const float* ob = (const float*)d_in[2];
    const float* mw = (const float*)d_in[3];
    const float* mb = (const float*)d_in[4];
    const float* dw = (const float*)d_in[5];
    const float* db = (const float*)d_in[6];
    float* out = (float*)d_out;

    cudaFuncSetAttribute(fused_kernel,
                         cudaFuncAttributeMaxDynamicSharedMemorySize, SMEM_F);

    prep_all_kernel<<<(Cc * CK + 9 * 64 * 32 + 255) / 256, 256>>>(dw, ow, mw);
    fused_kernel<<<(Bb * HW) / 128, 256, SMEM_F>>>(x, ob, mb, db, out);
}

// round 13
// speedup vs baseline: 1.4772x; 1.4772x over previous
#include <cuda_runtime.h>
#include <cuda_fp16.h>
#include <cstdint>
#include <math.h>

#define Bb  8
#define Cc  64
#define Hh  128
#define Ww  128
#define HW  (Hh*Ww)
#define K2  9
#define OCT 27
#define CK  (Cc*K2)     // 576

// ---------------------------------------------------------------------------
// helpers
// ---------------------------------------------------------------------------
__device__ __forceinline__ uint32_t smem_to_u32(const void* p) {
    uint32_t a;
    asm("{ .reg .u64 t; cvta.to.shared.u64 t, %1; cvt.u32.u64 %0, t; }"
        : "=r"(a) : "l"(p));
    return a;
}
#define LDSM_X4(r, ad) \
    asm volatile("ldmatrix.sync.aligned.m8n8.x4.shared.b16 {%0,%1,%2,%3}, [%4];" \
        : "=r"((r)[0]), "=r"((r)[1]), "=r"((r)[2]), "=r"((r)[3]) : "r"(ad))
#define LDSM_X4T(r, ad) \
    asm volatile("ldmatrix.sync.aligned.m8n8.x4.trans.shared.b16 {%0,%1,%2,%3}, [%4];" \
        : "=r"((r)[0]), "=r"((r)[1]), "=r"((r)[2]), "=r"((r)[3]) : "r"(ad))
#define STS128(ad, r0, r1, r2, r3) \
    asm volatile("st.shared.v4.b32 [%0], {%1,%2,%3,%4};" \
        :: "r"(ad), "r"(r0), "r"(r1), "r"(r2), "r"(r3) : "memory")
#define MMA_F16(d, a, b0, b1) \
    asm volatile("mma.sync.aligned.m16n8k16.row.col.f32.f16.f16.f32 " \
        "{%0,%1,%2,%3}, {%4,%5,%6,%7}, {%8,%9}, {%0,%1,%2,%3};" \
        : "+f"((d)[0]), "+f"((d)[1]), "+f"((d)[2]), "+f"((d)[3]) \
        : "r"((a)[0]), "r"((a)[1]), "r"((a)[2]), "r"((a)[3]), "r"(b0), "r"(b1))
__device__ __forceinline__ void cp_async16(uint32_t dst, const void* src) {
    asm volatile("cp.async.cg.shared.global [%0], [%1], 16;"
                 :: "r"(dst), "l"(src) : "memory");
}
#define CP_COMMIT() asm volatile("cp.async.commit_group;" ::: "memory")
#define CP_WAIT1()  asm volatile("cp.async.wait_group 1;" ::: "memory")
#define CP_WAIT0()  asm volatile("cp.async.wait_group 0;" ::: "memory")

// ---------------------------------------------------------------------------
// pre-swizzled fp16 B tiles: [9 chunks][64 k-rows(c) x 64 cols], 128B rows, SW128.
__device__ uint4 g_Bf4[9*8192/16];    // deform weights
__device__ uint4 g_BOf4[9*8192/16];   // offset+mask weights (cols 0..26 used)

// ---------------------------------------------------------------------------
// Merged weight prep: fp16, k-major chunks, SW128 pre-swizzled.
__global__ void prep_all_kernel(const float* __restrict__ dw,
                                const float* __restrict__ ow,
                                const float* __restrict__ mw) {
    int i = blockIdx.x * 256 + threadIdx.x;
    if (i < Cc * CK) {
        int o = i / CK;
        int r = i - o * CK;
        int c = r / 9;
        int k = r - c * 9;
        uint32_t off = (uint32_t)c * 128u + (uint32_t)o * 2u;
        uint32_t sw  = off ^ ((off >> 3) & 0x70u);
        ((__half*)g_Bf4)[k * 4096 + (sw >> 1)] = __float2half(dw[i]);
        return;
    }
    i -= Cc * CK;
    if (i >= 9 * 64 * 32) return;
    int k = i >> 11;
    int c = (i >> 5) & 63;
    int j = i & 31;
    float v = 0.f;
    if (j < 18)      v = ow[j * CK + c * 9 + k];
    else if (j < 27) v = mw[(j - 18) * CK + c * 9 + k];
    uint32_t off = (uint32_t)c * 128u + (uint32_t)j * 2u;
    uint32_t sw  = off ^ ((off >> 3) & 0x70u);
    ((__half*)g_BOf4)[k * 4096 + (sw >> 1)] = __float2half(v);
}

// ---------------------------------------------------------------------------
// smem layout (per CTA, 46592 B -> 2 CTAs/SM by regs):
//   [0, 16384)       B double-buffer: buf*8192
//   [16384, 32768)   A (128 rows x 128B = 64 fp16 cols, SW128)
//   [32768, 46592)   s_dy/s_dx/s_mk (128 px x 9 floats each)
#define SM_A    16384
#define SM_OFF  32768
#define SMEM_F  46592

// prefetch one 8KB fp16 chunk into buffer `buf` via cp.async
__device__ __forceinline__ void prefetch_chunk(uint32_t smem_base, int buf,
                                               const uint4* __restrict__ Bf,
                                               int ch, int tid) {
    const uint32_t dst = smem_base + (uint32_t)buf * 8192u;
    const uint4* s = Bf + ch * 512;
#pragma unroll
    for (int r = 0; r < 2; r++) {
        int i = tid + r * 256;
        cp_async16(dst + (uint32_t)i * 16u, s + i);
    }
    CP_COMMIT();
}

// ---------------------------------------------------------------------------
// Fused offset/mask conv + deformable conv, fp16 single-product MMA.
// Round-10 structure: two barriers per chunk, single A buffer, B double-buffer.
__global__ __launch_bounds__(256, 2)
void fused_kernel(const float* __restrict__ x,
                  const float* __restrict__ obias,
                  const float* __restrict__ mbias,
                  const float* __restrict__ db,
                  float* __restrict__ out)
{
    extern __shared__ char smd[];
    const uint32_t smem_base = smem_to_u32(smd);
    const int tid = threadIdx.x;

    // sampling-role mapping
    const int set = tid >> 7;        // channel half (32 ch)
    const int p   = tid & 127;       // pixel row within CTA
    const int pixel = blockIdx.x * 128 + p;
    const int b  = pixel >> 14;
    const int hw = pixel & (HW - 1);
    const int h  = hw >> 7;
    const int w  = hw & 127;
    const float* xb = x + (size_t)b * Cc * HW + (size_t)(set * 32) * HW;
    const uint32_t a_row_byte = (uint32_t)p * 128u;
    const uint32_t a_row_sw   = ((uint32_t)(p & 7)) << 4;

    // MMA-role mapping
    const int wid  = tid >> 5;
    const int lane = tid & 31;
    const int m0   = wid * 16;
    const uint32_t lm_arow  = (uint32_t)(m0 + (lane & 15));
    const uint32_t lm_asub  = ((uint32_t)(lane >> 4) & 1u) * 16u;
    const uint32_t lm_asw   = (lm_arow & 7u) << 4;
    const uint32_t lm_abase = lm_arow * 128u;
    const uint32_t lm_bkrow = (uint32_t)(lane & 15);
    const uint32_t lm_bnsub = ((uint32_t)(lane >> 4) & 1u) * 16u;

    float* s_dy = (float*)(smd + SM_OFF);
    float* s_dx = s_dy + 1152;
    float* s_mk = s_dx + 1152;

    // prologue: BO chunk 0 -> buf0
    prefetch_chunk(smem_base, 0, g_BOf4, 0, tid);

    // ======================= PHASE 1: offset + mask =======================
    {
        float acc[4][4];
#pragma unroll
        for (int n = 0; n < 4; n++)
#pragma unroll
            for (int q = 0; q < 4; q++) acc[n][q] = 0.f;

        for (int ch = 0; ch < 9; ch++) {
            const int hh = h + ch / 3 - 1;
            const int ww = w + ch % 3 - 1;
            const bool ok = ((unsigned)hh < (unsigned)Hh) && ((unsigned)ww < (unsigned)Ww);
            const int ioff = hh * Ww + ww;

            uint32_t a16[16];
            {
                const float* xc = xb;
#pragma unroll
                for (int i = 0; i < 16; i++) {
                    float s0 = ok ? xc[ioff] : 0.f;  xc += HW;
                    float s1 = ok ? xc[ioff] : 0.f;  xc += HW;
                    __half2 hp = __floats2half2_rn(s0, s1);
                    a16[i] = *(uint32_t*)&hp;
                }
            }

            __syncthreads();   // B1: prior MMAs done -> safe to refill buffers / A
            if (ch < 8) prefetch_chunk(smem_base, (ch + 1) & 1, g_BOf4, ch + 1, tid);
            else        prefetch_chunk(smem_base, 1, g_Bf4, 0, tid);  // bridge

#pragma unroll
            for (int u = 0; u < 4; u++) {
                uint32_t col = (((uint32_t)set * 64u) + (uint32_t)u * 16u) ^ a_row_sw;
                STS128(smem_base + SM_A + a_row_byte + col,
                       a16[u*4+0], a16[u*4+1], a16[u*4+2], a16[u*4+3]);
            }
            CP_WAIT1();        // chunk ch landed (next chunk may be in flight)
            __syncthreads();   // B2: A stores + everyone's cp.async visible

            const uint32_t bh_base = smem_base + (uint32_t)(ch & 1) * 8192u;
#pragma unroll
            for (int ks = 0; ks < 4; ks++) {
                uint32_t kcol = (((uint32_t)ks * 32u) + lm_asub) ^ lm_asw;
                uint32_t af[4];
                LDSM_X4(af, smem_base + SM_A + lm_abase + kcol);
                const uint32_t brow = (uint32_t)ks * 16u + lm_bkrow;
                const uint32_t bsw  = (brow & 7u) << 4;
                const uint32_t boff = brow * 128u;
                uint32_t bf[4];
                uint32_t ncol = lm_bnsub ^ bsw;
                LDSM_X4T(bf, bh_base + boff + ncol);
                MMA_F16(acc[0], af, bf[0], bf[1]);
                MMA_F16(acc[1], af, bf[2], bf[3]);
                uint32_t ncol2 = (32u + lm_bnsub) ^ bsw;
                LDSM_X4T(bf, bh_base + boff + ncol2);
                MMA_F16(acc[2], af, bf[0], bf[1]);
                MMA_F16(acc[3], af, bf[2], bf[3]);
            }
        }

        // epilogue -> smem dy/dx/mask
        const int r0 = m0 + (lane >> 2);
#pragma unroll
        for (int nt = 0; nt < 4; nt++) {
            const int j0 = nt * 8 + (lane & 3) * 2;
#pragma unroll
            for (int q = 0; q < 4; q++) {
                const int j = j0 + (q & 1);
                if (j >= 27) continue;
                const int P = r0 + ((q >> 1) << 3);
                const float v = acc[nt][q];
                if (j < 18) {
                    float t = v + obias[j];
                    if ((j & 1) == 0) s_dy[P * 9 + (j >> 1)] = t;
                    else              s_dx[P * 9 + (j >> 1)] = t;
                } else {
                    float z = v + mbias[j - 18];
                    s_mk[P * 9 + (j - 18)] = 1.f / (1.f + expf(-z));
                }
            }
        }
    }
    __syncthreads();   // offsets visible to deform sampling

    // ========================= PHASE 2: deform ===========================
    float acc2[8][4];
#pragma unroll
    for (int n = 0; n < 8; n++)
#pragma unroll
        for (int q = 0; q < 4; q++) acc2[n][q] = 0.f;

    for (int ch = 0; ch < 9; ch++) {
        const int k = ch;
        const float m  = s_mk[p * 9 + k];
        const float py = (float)(h + k / 3 - 1) + s_dy[p * 9 + k];
        const float px = (float)(w + k % 3 - 1) + s_dx[p * 9 + k];
        const float yf = floorf(py), xf = floorf(px);
        const int   y0 = (int)yf,  x0 = (int)xf;
        const float ly = py - yf,  lx = px - xf;
        const bool y0v = (unsigned)y0       < (unsigned)Hh;
        const bool y1v = (unsigned)(y0 + 1) < (unsigned)Hh;
        const bool x0v = (unsigned)x0       < (unsigned)Ww;
        const bool x1v = (unsigned)(x0 + 1) < (unsigned)Ww;
        const float w00 = (y0v && x0v) ? (1.f - ly) * (1.f - lx) * m : 0.f;
        const float w01 = (y0v && x1v) ? (1.f - ly) * lx         * m : 0.f;
        const float w10 = (y1v && x0v) ? ly         * (1.f - lx) * m : 0.f;
        const float w11 = (y1v && x1v) ? ly         * lx         * m : 0.f;
        const int cy0 = min(max(y0, 0), Hh - 1), cy1 = min(max(y0 + 1, 0), Hh - 1);
        const int cx0 = min(max(x0, 0), Ww - 1), cx1 = min(max(x0 + 1, 0), Ww - 1);
        const int i00 = cy0 * Ww + cx0, i01 = cy0 * Ww + cx1;
        const int i10 = cy1 * Ww + cx0, i11 = cy1 * Ww + cx1;

        uint32_t a16[16];
        {
            const float* xc = xb;
#pragma unroll
            for (int i = 0; i < 16; i++) {
                float s0 = w00 * xc[i00] + w01 * xc[i01] + w10 * xc[i10] + w11 * xc[i11];
                xc += HW;
                float s1 = w00 * xc[i00] + w01 * xc[i01] + w10 * xc[i10] + w11 * xc[i11];
                xc += HW;
                __half2 hp = __floats2half2_rn(s0, s1);
                a16[i] = *(uint32_t*)&hp;
            }
        }

        __syncthreads();   // B1
        if (ch < 8) prefetch_chunk(smem_base, ch & 1, g_Bf4, ch + 1, tid);

#pragma unroll
        for (int u = 0; u < 4; u++) {
            uint32_t col = (((uint32_t)set * 64u) + (uint32_t)u * 16u) ^ a_row_sw;
            STS128(smem_base + SM_A + a_row_byte + col,
                   a16[u*4+0], a16[u*4+1], a16[u*4+2], a16[u*4+3]);
        }
        if (ch < 8) { CP_WAIT1(); } else { CP_WAIT0(); }
        __syncthreads();   // B2

        // deform chunk ch lives in buf (ch+1)&1 (bridge put chunk0 in buf1)
        const uint32_t bh_base = smem_base + (uint32_t)((ch + 1) & 1) * 8192u;
#pragma unroll
        for (int ks = 0; ks < 4; ks++) {
            uint32_t kcol = (((uint32_t)ks * 32u) + lm_asub) ^ lm_asw;
            uint32_t af[4];
            LDSM_X4(af, smem_base + SM_A + lm_abase + kcol);
            const uint32_t brow = (uint32_t)ks * 16u + lm_bkrow;
            const uint32_t bsw  = (brow & 7u) << 4;
            const uint32_t boff = brow * 128u;
#pragma unroll
            for (int nt2 = 0; nt2 < 4; nt2++) {
                uint32_t ncol = (((uint32_t)nt2 * 32u) + lm_bnsub) ^ bsw;
                uint32_t bf[4];
                LDSM_X4T(bf, bh_base + boff + ncol);
                MMA_F16(acc2[2*nt2],     af, bf[0], bf[1]);
                MMA_F16(acc2[2*nt2 + 1], af, bf[2], bf[3]);
            }
        }
    }

    // ---- epilogue: acc2 fragment -> out[b][o][hw] (+bias) ----
    const int pix0 = blockIdx.x * 128;
    const int bB   = pix0 >> 14;
    const int hw0  = (pix0 & (HW - 1)) + m0 + (lane >> 2);
    float* ob = out + (size_t)bB * Cc * HW;
#pragma unroll
    for (int nt = 0; nt < 8; nt++) {
        const int ch0 = nt * 8 + (lane & 3) * 2;
        const float b0 = db[ch0], b1 = db[ch0 + 1];
        ob[(size_t)ch0       * HW + hw0]     = acc2[nt][0] + b0;
        ob[(size_t)(ch0 + 1) * HW + hw0]     = acc2[nt][1] + b1;
        ob[(size_t)ch0       * HW + hw0 + 8] = acc2[nt][2] + b0;
        ob[(size_t)(ch0 + 1) * HW + hw0 + 8] = acc2[nt][3] + b1;
    }
}

// ---------------------------------------------------------------------------
extern "C" void kernel_launch(void* const* d_in, const int* in_sizes, int n_in,
                              void* d_out, int out_size)
{
    const float* x  = (const float*)d_in[0];
    const float* ow = (const float*)d_in[1];
    const float* ob = (const float*)d_in[2];
    const float* mw = (const float*)d_in[3];
    const float* mb = (const float*)d_in[4];
    const float* dw = (const float*)d_in[5];
    const float* db = (const float*)d_in[6];
    float* out = (float*)d_out;

    cudaFuncSetAttribute(fused_kernel,
                         cudaFuncAttributeMaxDynamicSharedMemorySize, SMEM_F);

    prep_all_kernel<<<(Cc * CK + 9 * 64 * 32 + 255) / 256, 256>>>(dw, ow, mw);
    fused_kernel<<<(Bb * HW) / 128, 256, SMEM_F>>>(x, ob, mb, db, out);
}